// round 3
// baseline (speedup 1.0000x reference)
#include <cuda_runtime.h>
#include <cstdint>

#define BTOT 16384
#define T    28
#define INP  28
#define H    64
#define G    256   // 4*H gates
#define RB   32    // batch rows per block
#define NT   256   // threads per block
#define OUTD 10
#define NQ   23    // 7 x-chunks (28 floats) + 16 h-chunks (64 floats), 4 floats each

typedef unsigned long long ull;

// Weights repacked [chunk][gate] as float4 so per-warp weight loads are fully
// coalesced LDG.128 (32 lanes x 16B consecutive). Stays L1-resident (~94KB).
__device__ float4 g_wpack[NQ * G];
__device__ float  g_bias[G];

__global__ void repack_kernel(const float* __restrict__ W_ih,
                              const float* __restrict__ W_hh,
                              const float* __restrict__ b_ih,
                              const float* __restrict__ b_hh) {
    int g = blockIdx.x * blockDim.x + threadIdx.x;
    if (g >= G) return;
    g_bias[g] = b_ih[g] + b_hh[g];
    const float* wi = W_ih + g * INP;
#pragma unroll
    for (int q = 0; q < 7; q++)
        g_wpack[q * G + g] = make_float4(wi[4*q], wi[4*q+1], wi[4*q+2], wi[4*q+3]);
    const float* wh = W_hh + g * H;
#pragma unroll
    for (int q = 0; q < 16; q++)
        g_wpack[(7 + q) * G + g] = make_float4(wh[4*q], wh[4*q+1], wh[4*q+2], wh[4*q+3]);
}

// Packed dual-FMA: 2 fp32 MACs per instruction (fma pipe runs 2x vs scalar FFMA).
__device__ __forceinline__ void fma2(ull& d, ull a, ull b) {
    asm("fma.rn.f32x2 %0, %1, %2, %0;" : "+l"(d) : "l"(a), "l"(b));
}

__device__ __forceinline__ float sigm(float x) {
    return __fdividef(1.0f, 1.0f + __expf(-x));
}
__device__ __forceinline__ float tanh_(float x) {
    // 2*sigmoid(2x)-1; __expf overflow to inf gives exact saturation to -1/+1.
    return __fdividef(2.0f, 1.0f + __expf(-2.0f * x)) - 1.0f;
}

__global__ void __launch_bounds__(NT, 2) lstm_kernel(
    const float* __restrict__ x,
    const float* __restrict__ W_fc,
    const float* __restrict__ b_fc,
    float* __restrict__ out)
{
    __shared__ __align__(16) float x_sh[RB * INP];    //  3.5 KB: this step's x slice
    __shared__ __align__(16) float h_sh[RB * H];      //  8   KB: hidden state
    __shared__ __align__(16) float gates_sh[RB * G];  // 32   KB: pre-activation gates

    const int g  = threadIdx.x;        // gate column owned by this thread
    const int b0 = blockIdx.x * RB;    // first batch row of this block
    const float bias = g_bias[g];
    const int j  = g & (H - 1);        // hidden unit for elementwise phase
    const int rg = g >> 6;             // row-group (0..3) for elementwise phase

    for (int i = g; i < RB * H; i += NT) h_sh[i] = 0.0f;
    float c[8];
#pragma unroll
    for (int m = 0; m < 8; m++) c[m] = 0.0f;

    const ulonglong2* wp = reinterpret_cast<const ulonglong2*>(g_wpack);
    const ulonglong2* xs = reinterpret_cast<const ulonglong2*>(x_sh);
    const ulonglong2* hs = reinterpret_cast<const ulonglong2*>(h_sh);

    for (int t = 0; t < T; t++) {
        // ---- stage this timestep's x slice: x[b0+r][t][0..27] -> x_sh[r][i] ----
        for (int idx = g; idx < RB * INP; idx += NT) {
            int r  = idx / INP;
            int i2 = idx - r * INP;
            x_sh[idx] = x[((size_t)(b0 + r) * T + t) * INP + i2];
        }
        __syncthreads();   // x_sh ready; h_sh from previous step ready

        // ---- gate phase: acc[r] = W_ih[g]·x[r] + W_hh[g]·h[r]  (packed f32x2) ----
        ull acc[RB];
#pragma unroll
        for (int r = 0; r < RB; r++) acc[r] = 0ull;

#pragma unroll
        for (int q = 0; q < 7; q++) {              // x part (28 floats)
            ulonglong2 w = wp[q * G + g];          // coalesced LDG.128, L1-hit
#pragma unroll
            for (int r = 0; r < RB; r++) {
                ulonglong2 v = xs[r * 7 + q];      // broadcast LDS.128
                fma2(acc[r], w.x, v.x);
                fma2(acc[r], w.y, v.y);
            }
        }
#pragma unroll
        for (int q = 0; q < 16; q++) {             // h part (64 floats)
            ulonglong2 w = wp[(7 + q) * G + g];
#pragma unroll
            for (int r = 0; r < RB; r++) {
                ulonglong2 v = hs[r * 16 + q];     // broadcast LDS.128
                fma2(acc[r], w.x, v.x);
                fma2(acc[r], w.y, v.y);
            }
        }
#pragma unroll
        for (int r = 0; r < RB; r++) {
            float2 f = *reinterpret_cast<float2*>(&acc[r]);
            gates_sh[r * G + g] = f.x + f.y + bias;
        }
        __syncthreads();   // gates ready

        // ---- elementwise phase: thread handles hidden unit j for 8 rows ----
#pragma unroll
        for (int m = 0; m < 8; m++) {
            int r = rg + 4 * m;
            float gi = gates_sh[r * G + j];
            float gf = gates_sh[r * G + H + j];
            float gg = gates_sh[r * G + 2 * H + j];
            float go = gates_sh[r * G + 3 * H + j];
            float cm = sigm(gf) * c[m] + sigm(gi) * tanh_(gg);
            c[m] = cm;
            h_sh[r * H + j] = sigm(go) * tanh_(cm);
        }
        // no sync needed here: next iteration's first sync (after x staging)
        // orders h_sh writes before the next gate phase reads them.
    }

    __syncthreads();   // final h_sh ready

    // ---- fused FC epilogue: out[r][o] = h[r]·W_fc[o] + b_fc[o] ----
    for (int idx = g; idx < RB * OUTD; idx += NT) {
        int r = idx / OUTD;
        int o = idx - r * OUTD;
        float a = b_fc[o];
        const float* wf = W_fc + o * H;
#pragma unroll
        for (int k = 0; k < H; k++) a += h_sh[r * H + k] * wf[k];
        out[(size_t)(b0 + r) * OUTD + o] = a;
    }
}

extern "C" void kernel_launch(void* const* d_in, const int* in_sizes, int n_in,
                              void* d_out, int out_size) {
    const float* x    = (const float*)d_in[0];
    const float* W_ih = (const float*)d_in[1];
    const float* W_hh = (const float*)d_in[2];
    const float* b_ih = (const float*)d_in[3];
    const float* b_hh = (const float*)d_in[4];
    const float* W_fc = (const float*)d_in[5];
    const float* b_fc = (const float*)d_in[6];

    repack_kernel<<<1, 256>>>(W_ih, W_hh, b_ih, b_hh);
    lstm_kernel<<<BTOT / RB, NT>>>(x, W_fc, b_fc, (float*)d_out);
}

// round 5
// speedup vs baseline: 2.3242x; 2.3242x over previous
#include <cuda_runtime.h>
#include <cstdint>

#define BTOT 16384
#define T    28
#define INP  28
#define H    64
#define G    256   // 4*H gates
#define RB   32    // batch rows per block
#define NT   256   // threads per block
#define OUTD 10
#define NQ   23    // 7 x-chunks + 16 h-chunks of 4 floats

typedef unsigned long long ull;

// Weights repacked [chunk q][gate 0..3][unit j] as float4 so the 4 gate-chunks a
// thread needs are 4 coalesced LDG.128 (lanes j consecutive, 512B/warp), all
// L1-resident (~94KB, shared addresses across row-groups and blocks).
__device__ float4 g_wpack[NQ * 4 * H];
__device__ float  g_bias[G];

__global__ void repack_kernel(const float* __restrict__ W_ih,
                              const float* __restrict__ W_hh,
                              const float* __restrict__ b_ih,
                              const float* __restrict__ b_hh) {
    int g = blockIdx.x * blockDim.x + threadIdx.x;   // original gate row 0..255
    if (g >= G) return;
    g_bias[g] = b_ih[g] + b_hh[g];
    int gt = g >> 6;          // gate class i/f/g/o
    int j  = g & (H - 1);     // hidden unit
    const float* wi = W_ih + g * INP;
#pragma unroll
    for (int q = 0; q < 7; q++)
        g_wpack[(q * 4 + gt) * H + j] =
            make_float4(wi[4*q], wi[4*q+1], wi[4*q+2], wi[4*q+3]);
    const float* wh = W_hh + g * H;
#pragma unroll
    for (int q = 0; q < 16; q++)
        g_wpack[((7 + q) * 4 + gt) * H + j] =
            make_float4(wh[4*q], wh[4*q+1], wh[4*q+2], wh[4*q+3]);
}

// Packed dual-FMA: 2 fp32 MACs per instruction.
__device__ __forceinline__ void fma2(ull& d, ull a, ull b) {
    asm("fma.rn.f32x2 %0, %1, %2, %0;" : "+l"(d) : "l"(a), "l"(b));
}

// Single-MUFU tanh (sm_75+), ~1e-4 worst-case abs error — far inside tolerance.
__device__ __forceinline__ float tanha(float x) {
    float y; asm("tanh.approx.f32 %0, %1;" : "=f"(y) : "f"(x)); return y;
}
__device__ __forceinline__ float sigm(float x) {
    return fmaf(0.5f, tanha(0.5f * x), 0.5f);
}

__global__ void __launch_bounds__(NT, 2) lstm_kernel(
    const float* __restrict__ x,
    const float* __restrict__ W_fc,
    const float* __restrict__ b_fc,
    float* __restrict__ out)
{
    __shared__ __align__(16) float x_sh[2][RB * INP];  // 7 KB, double-buffered
    __shared__ __align__(16) float h_sh[2][RB * H];    // 16 KB, double-buffered

    const int tid = threadIdx.x;
    const int j   = tid & (H - 1);   // hidden unit owned by this thread
    const int rg  = tid >> 6;        // row-group 0..3
    const int r0  = rg * 8;          // first of this thread's 8 rows
    const int b0  = blockIdx.x * RB;

    float bias[4];
#pragma unroll
    for (int gt = 0; gt < 4; gt++) bias[gt] = g_bias[gt * H + j];

    // initial state: stage x[0] into buf0, zero h buf0
    for (int idx = tid; idx < RB * INP; idx += NT) {
        int r = idx / INP, i2 = idx - r * INP;
        x_sh[0][idx] = x[((size_t)(b0 + r) * T) * INP + i2];
    }
    for (int idx = tid; idx < RB * H; idx += NT) h_sh[0][idx] = 0.0f;

    float c[8];
#pragma unroll
    for (int m = 0; m < 8; m++) c[m] = 0.0f;

    const ulonglong2* wp = reinterpret_cast<const ulonglong2*>(g_wpack);

    for (int t = 0; t < T; t++) {
        __syncthreads();   // x_sh[t&1], h_sh[t&1] ready

        // ---- prefetch x[t+1] into registers (latency hidden under FMAs) ----
        float xpre[4];
        int tn = (t + 1 < T) ? t + 1 : t;
#pragma unroll
        for (int u = 0; u < 4; u++) {
            int idx = tid + u * NT;
            if (idx < RB * INP) {
                int r = idx / INP, i2 = idx - r * INP;
                xpre[u] = x[((size_t)(b0 + r) * T + tn) * INP + i2];
            }
        }

        const ulonglong2* xs = reinterpret_cast<const ulonglong2*>(x_sh[t & 1]);
        const ulonglong2* hs = reinterpret_cast<const ulonglong2*>(h_sh[t & 1]);

        // ---- gate phase: all 4 gates of unit j, 8 rows, packed f32x2 ----
        ull acc[4][8];
#pragma unroll
        for (int gt = 0; gt < 4; gt++)
#pragma unroll
            for (int r = 0; r < 8; r++) acc[gt][r] = 0ull;

#pragma unroll
        for (int q = 0; q < 7; q++) {                 // x part (28 floats)
            ulonglong2 w[4];
#pragma unroll
            for (int gt = 0; gt < 4; gt++) w[gt] = wp[(q * 4 + gt) * H + j];
#pragma unroll
            for (int r = 0; r < 8; r++) {
                ulonglong2 v = xs[(r0 + r) * 7 + q];  // broadcast LDS.128
#pragma unroll
                for (int gt = 0; gt < 4; gt++) {
                    fma2(acc[gt][r], w[gt].x, v.x);
                    fma2(acc[gt][r], w[gt].y, v.y);
                }
            }
        }
#pragma unroll
        for (int q = 0; q < 16; q++) {                // h part (64 floats)
            ulonglong2 w[4];
#pragma unroll
            for (int gt = 0; gt < 4; gt++) w[gt] = wp[((7 + q) * 4 + gt) * H + j];
#pragma unroll
            for (int r = 0; r < 8; r++) {
                ulonglong2 v = hs[(r0 + r) * 16 + q]; // broadcast LDS.128
#pragma unroll
                for (int gt = 0; gt < 4; gt++) {
                    fma2(acc[gt][r], w[gt].x, v.x);
                    fma2(acc[gt][r], w[gt].y, v.y);
                }
            }
        }

        // ---- elementwise: gates live in registers, no smem round-trip ----
        float* hn = h_sh[(t + 1) & 1];
#pragma unroll
        for (int r = 0; r < 8; r++) {
            float s[4];
#pragma unroll
            for (int gt = 0; gt < 4; gt++) {
                float2 f2 = *reinterpret_cast<float2*>(&acc[gt][r]);
                s[gt] = f2.x + f2.y + bias[gt];
            }
            float ig = sigm(s[0]);
            float fg = sigm(s[1]);
            float gg = tanha(s[2]);
            float og = sigm(s[3]);
            float cm = fmaf(fg, c[r], ig * gg);
            c[r] = cm;
            hn[(r0 + r) * H + j] = og * tanha(cm);
        }

        // ---- commit x prefetch into the (t+1) buffer ----
        float* xn = x_sh[(t + 1) & 1];
#pragma unroll
        for (int u = 0; u < 4; u++) {
            int idx = tid + u * NT;
            if (idx < RB * INP) xn[idx] = xpre[u];
        }
        // single barrier per step: top of next iteration orders everything
    }

    __syncthreads();   // final h in h_sh[T&1] == h_sh[0]

    // ---- fused FC epilogue: out[r][o] = h[r]·W_fc[o] + b_fc[o] ----
    const float* hf = h_sh[T & 1];
    for (int idx = tid; idx < RB * OUTD; idx += NT) {
        int r = idx / OUTD;
        int o = idx - r * OUTD;
        float a = b_fc[o];
        const float* wf = W_fc + o * H;
#pragma unroll
        for (int k = 0; k < H; k++) a += hf[r * H + k] * wf[k];
        out[(size_t)(b0 + r) * OUTD + o] = a;
    }
}

extern "C" void kernel_launch(void* const* d_in, const int* in_sizes, int n_in,
                              void* d_out, int out_size) {
    const float* x    = (const float*)d_in[0];
    const float* W_ih = (const float*)d_in[1];
    const float* W_hh = (const float*)d_in[2];
    const float* b_ih = (const float*)d_in[3];
    const float* b_hh = (const float*)d_in[4];
    const float* W_fc = (const float*)d_in[5];
    const float* b_fc = (const float*)d_in[6];

    repack_kernel<<<1, 256>>>(W_ih, W_hh, b_ih, b_hh);
    lstm_kernel<<<BTOT / RB, NT>>>(x, W_fc, b_fc, (float*)d_out);
}

// round 7
// speedup vs baseline: 6.2532x; 2.6904x over previous
#include <cuda_runtime.h>
#include <cuda_bf16.h>
#include <cstdint>

#define BTOT  16384
#define T     28
#define INP   28
#define H     64
#define MROWS 128
#define NT    256
#define OUTD  10

// ---- dynamic SMEM layout (byte offsets) ----
// A tiles: [rf 0..7][kf 0..5][lane 0..31][16B]  (fragment-major, bf16 pairs)
#define OFF_AHI 0
#define OFF_ALO 24576
// B tiles: [w 0..7][kf 0..5][nf 0..3][lane 0..31][8B]
#define OFF_BHI 49152
#define OFF_BLO 98304
#define SMEM_BYTES 147456
// epilogue reuse (regions dead after the loop): h_f32 at 0..32768
#define OFF_WFC  36864
#define OFF_BFC  39424
#define OFF_PART 40960

__device__ __forceinline__ uint32_t smem_u32(const void* p) {
    uint32_t a;
    asm("{ .reg .u64 t; cvta.to.shared.u64 t, %1; cvt.u32.u64 %0, t; }" : "=r"(a) : "l"(p));
    return a;
}
__device__ __forceinline__ void sts32(uint32_t a, uint32_t v) {
    asm volatile("st.shared.b32 [%0], %1;" :: "r"(a), "r"(v) : "memory");
}
__device__ __forceinline__ void lds128(uint32_t* r, uint32_t a) {
    asm volatile("ld.shared.v4.b32 {%0,%1,%2,%3}, [%4];"
                 : "=r"(r[0]), "=r"(r[1]), "=r"(r[2]), "=r"(r[3]) : "r"(a));
}
__device__ __forceinline__ void lds64(uint32_t* r, uint32_t a) {
    asm volatile("ld.shared.v2.b32 {%0,%1}, [%2];" : "=r"(r[0]), "=r"(r[1]) : "r"(a));
}

// split two f32 into packed bf16x2 hi + bf16x2 residual lo
__device__ __forceinline__ void split2(float a, float b, uint32_t& hi, uint32_t& lo) {
    __nv_bfloat162 h2; h2.x = __float2bfloat16_rn(a); h2.y = __float2bfloat16_rn(b);
    __nv_bfloat162 l2;
    l2.x = __float2bfloat16_rn(a - __bfloat162float(h2.x));
    l2.y = __float2bfloat16_rn(b - __bfloat162float(h2.y));
    hi = *reinterpret_cast<uint32_t*>(&h2);
    lo = *reinterpret_cast<uint32_t*>(&l2);
}

__device__ __forceinline__ float tanha(float x) {
    float y; asm("tanh.approx.f32 %0, %1;" : "=f"(y) : "f"(x)); return y;
}
__device__ __forceinline__ float sigm(float x) { return fmaf(0.5f, tanha(0.5f * x), 0.5f); }

// m16n8k16 bf16 MMA, D += A*B (C aliased to D)
__device__ __forceinline__ void mma16816(float* d, const uint32_t* a, const uint32_t* b) {
    asm volatile(
        "mma.sync.aligned.m16n8k16.row.col.f32.bf16.bf16.f32 "
        "{%0,%1,%2,%3}, {%4,%5,%6,%7}, {%8,%9}, {%0,%1,%2,%3};"
        : "+f"(d[0]), "+f"(d[1]), "+f"(d[2]), "+f"(d[3])
        : "r"(a[0]), "r"(a[1]), "r"(a[2]), "r"(a[3]), "r"(b[0]), "r"(b[1]));
}

// weight element with K mapping: k 0..27 -> W_ih, 28..31 -> 0, 32..95 -> W_hh
__device__ __forceinline__ float wval(const float* __restrict__ Wih,
                                      const float* __restrict__ Whh, int g, int k) {
    if (k < INP)  return Wih[g * INP + k];
    if (k < 32)   return 0.0f;
    return Whh[g * H + (k - 32)];
}

__global__ void __launch_bounds__(NT, 1) lstm_mma_kernel(
    const float* __restrict__ x,    const float* __restrict__ W_ih,
    const float* __restrict__ W_hh, const float* __restrict__ b_ih,
    const float* __restrict__ b_hh, const float* __restrict__ W_fc,
    const float* __restrict__ b_fc, float* __restrict__ out)
{
    extern __shared__ char sm[];
    const uint32_t sb  = smem_u32(sm);
    const int tid  = threadIdx.x;
    const int w    = tid >> 5;          // warp: owns gate-cols for units w*8..w*8+7
    const int lane = tid & 31;
    const int g8   = lane >> 2;         // groupID
    const int tig  = lane & 3;          // threadID in group
    const int b0   = blockIdx.x * MROWS;

    // ---- zero A tiles (covers x-pad k28..31 and h0 = 0) ----
    {
        uint4* az = reinterpret_cast<uint4*>(sm);
        uint4 z = make_uint4(0u, 0u, 0u, 0u);
        for (int i = tid; i < OFF_BHI / 16; i += NT) az[i] = z;
    }

    // ---- build B fragments (hi/lo), fragment-major ----
    // pair index: [w'][kf][nf][t'][reg]; value cols (k0,k0+1), col-in-frag u = t'/4
    for (int ii = tid; ii < 8 * 6 * 4 * 32 * 2; ii += NT) {
        int reg = ii & 1;
        int t_  = (ii >> 1) & 31;
        int nf  = (ii >> 6) & 3;
        int kfn = (ii >> 8);
        int kf  = kfn % 6;
        int w_  = kfn / 6;
        int k0  = kf * 16 + reg * 8 + 2 * (t_ & 3);
        int g   = nf * 64 + w_ * 8 + (t_ >> 2);
        float v0 = wval(W_ih, W_hh, g, k0);
        float v1 = wval(W_ih, W_hh, g, k0 + 1);
        uint32_t hi, lo; split2(v0, v1, hi, lo);
        uint32_t boff = (uint32_t)(((w_ * 6 + kf) * 4 + nf) * 256 + t_ * 8 + reg * 4);
        sts32(sb + OFF_BHI + boff, hi);
        sts32(sb + OFF_BLO + boff, lo);
    }

    // ---- per-thread bias (gate nf, unit offset u = 2*tig + ul) ----
    float bias2[4][2];
#pragma unroll
    for (int nf = 0; nf < 4; nf++)
#pragma unroll
        for (int ul = 0; ul < 2; ul++) {
            int g = nf * 64 + w * 8 + 2 * tig + ul;
            bias2[nf][ul] = b_ih[g] + b_hh[g];
        }

    // ---- x staging map: 7 pairs/thread over [128 rows x 14 pairs] ----
    int      xgb[7];     // global element offset base: (b0+r)*T*INP + kp
    uint32_t xsa[7];     // smem byte offset inside an A tile
#pragma unroll
    for (int i = 0; i < 7; i++) {
        int p  = tid + i * NT;
        int r  = p / 14;
        int kp = (p % 14) * 2;
        xgb[i] = ((b0 + r) * T) * INP + kp;
        int rf = r >> 4, gp = r & 7, rh = (r >> 3) & 1;
        int kf = kp >> 4, ki = kp & 15;
        xsa[i] = (uint32_t)((rf * 6 + kf) * 512 + (gp * 4 + ((ki & 7) >> 1)) * 16
                            + (ki >> 3) * 8 + rh * 4);
    }

    __syncthreads();   // zeroing complete before x(0) staging

    // ---- stage x(0) ----
#pragma unroll
    for (int i = 0; i < 7; i++) {
        float2 v = *reinterpret_cast<const float2*>(x + xgb[i]);
        uint32_t hi, lo; split2(v.x, v.y, hi, lo);
        sts32(sb + OFF_AHI + xsa[i], hi);
        sts32(sb + OFF_ALO + xsa[i], lo);
    }

    // ---- h writeback base address (k0h = 32 + w*8 + 2*tig) ----
    const int k0h = 32 + w * 8 + 2 * tig;
    const uint32_t hbase = (uint32_t)(((k0h >> 4) * 32 + g8 * 4 + ((k0h & 7) >> 1)) * 16
                                      + ((k0h >> 3) & 1) * 8);

    float c[32];
#pragma unroll
    for (int i = 0; i < 32; i++) c[i] = 0.0f;

    // =========================== timestep loop ===============================
    for (int t = 0; t < T; t++) {
        __syncthreads();   // A(t) fully staged (h + x writes visible)

        // ---- D init = bias (accumulates bias without a K extension) ----
        float d[8][4][4];
#pragma unroll
        for (int rf = 0; rf < 8; rf++)
#pragma unroll
            for (int nf = 0; nf < 4; nf++)
#pragma unroll
                for (int sl = 0; sl < 4; sl++)
                    d[rf][nf][sl] = bias2[nf][sl & 1];

        // ---- MMA phase: 3 terms (Ahi*Bhi + Alo*Bhi + Ahi*Blo) ----
#pragma unroll
        for (int kf = 0; kf < 6; kf++) {
            uint32_t bh[4][2], bl[4][2];
#pragma unroll
            for (int nf = 0; nf < 4; nf++) {
                uint32_t boff = (uint32_t)(((w * 6 + kf) * 4 + nf) * 256 + lane * 8);
                lds64(bh[nf], sb + OFF_BHI + boff);
                lds64(bl[nf], sb + OFF_BLO + boff);
            }
#pragma unroll
            for (int rf = 0; rf < 8; rf++) {
                uint32_t aoff = (uint32_t)((rf * 6 + kf) * 512 + lane * 16);
                uint32_t ah[4], al[4];
                lds128(ah, sb + OFF_AHI + aoff);
                lds128(al, sb + OFF_ALO + aoff);
#pragma unroll
                for (int nf = 0; nf < 4; nf++) {
                    mma16816(d[rf][nf], ah, bh[nf]);
                    mma16816(d[rf][nf], al, bh[nf]);
                    mma16816(d[rf][nf], ah, bl[nf]);
                }
            }
        }

        // ---- prefetch x(t+1) (consumed after the sync) ----
        float2 xp[7];
        if (t < T - 1) {
#pragma unroll
            for (int i = 0; i < 7; i++)
                xp[i] = *reinterpret_cast<const float2*>(x + xgb[i] + (t + 1) * INP);
        }

        __syncthreads();   // all A reads done -> safe to overwrite A

        // ---- eltwise (register-local gates) + h writeback ----
        const bool last = (t == T - 1);
#pragma unroll
        for (int rf = 0; rf < 8; rf++) {
#pragma unroll
            for (int rh = 0; rh < 2; rh++) {
                float hv[2];
#pragma unroll
                for (int ul = 0; ul < 2; ul++) {
                    int sl = 2 * rh + ul;
                    int ci = rf * 4 + sl;
                    float gi = sigm(d[rf][0][sl]);
                    float gf = sigm(d[rf][1][sl]);
                    float gg = tanha(d[rf][2][sl]);
                    float go = sigm(d[rf][3][sl]);
                    float cm = fmaf(gf, c[ci], gi * gg);
                    c[ci] = cm;
                    hv[ul] = go * tanha(cm);
                }
                if (!last) {
                    uint32_t hi, lo; split2(hv[0], hv[1], hi, lo);
                    uint32_t a = (uint32_t)(rf * 3072) + hbase + (uint32_t)(rh * 4);
                    sts32(sb + OFF_AHI + a, hi);
                    sts32(sb + OFF_ALO + a, lo);
                } else {
                    // final step: dump f32 h_last into [r][j] layout at smem base
                    int r  = rf * 16 + g8 + 8 * rh;
                    int j0 = w * 8 + 2 * tig;
                    float* hf = reinterpret_cast<float*>(sm);
                    hf[r * H + j0]     = hv[0];
                    hf[r * H + j0 + 1] = hv[1];
                }
            }
        }

        // ---- commit x(t+1) ----
        if (t < T - 1) {
#pragma unroll
            for (int i = 0; i < 7; i++) {
                uint32_t hi, lo; split2(xp[i].x, xp[i].y, hi, lo);
                sts32(sb + OFF_AHI + xsa[i], hi);
                sts32(sb + OFF_ALO + xsa[i], lo);
            }
        }
    }

    // ======================= FC epilogue (fp32 SIMT) =========================
    __syncthreads();
    float* smf = reinterpret_cast<float*>(sm);
    for (int i = tid; i < OUTD * H; i += NT) smf[OFF_WFC / 4 + i] = W_fc[i];
    if (tid < OUTD) smf[OFF_BFC / 4 + tid] = b_fc[tid];
    __syncthreads();
    {
        const int half = tid >> 7, rr = tid & 127;
        float acc[OUTD];
#pragma unroll
        for (int o = 0; o < OUTD; o++) acc[o] = 0.0f;
#pragma unroll
        for (int p = 0; p < 32; p++) {
            int k = half * 32 + p;
            float hvv = smf[rr * H + k];
#pragma unroll
            for (int o = 0; o < OUTD; o++)
                acc[o] = fmaf(hvv, smf[OFF_WFC / 4 + o * H + k], acc[o]);
        }
#pragma unroll
        for (int o = 0; o < OUTD; o++)
            smf[OFF_PART / 4 + (half * 128 + rr) * OUTD + o] = acc[o];
    }
    __syncthreads();
    for (int i = tid; i < MROWS * OUTD; i += NT) {
        int rr = i / OUTD, o = i - rr * OUTD;
        out[(size_t)(b0 + rr) * OUTD + o] =
            smf[OFF_PART / 4 + rr * OUTD + o]
          + smf[OFF_PART / 4 + (128 + rr) * OUTD + o]
          + smf[OFF_BFC / 4 + o];
    }
}

extern "C" void kernel_launch(void* const* d_in, const int* in_sizes, int n_in,
                              void* d_out, int out_size) {
    const float* x    = (const float*)d_in[0];
    const float* W_ih = (const float*)d_in[1];
    const float* W_hh = (const float*)d_in[2];
    const float* b_ih = (const float*)d_in[3];
    const float* b_hh = (const float*)d_in[4];
    const float* W_fc = (const float*)d_in[5];
    const float* b_fc = (const float*)d_in[6];

    cudaFuncSetAttribute(lstm_mma_kernel,
                         cudaFuncAttributeMaxDynamicSharedMemorySize, SMEM_BYTES);
    lstm_mma_kernel<<<BTOT / MROWS, NT, SMEM_BYTES>>>(
        x, W_ih, W_hh, b_ih, b_hh, W_fc, b_fc, (float*)d_out);
}